// round 11
// baseline (speedup 1.0000x reference)
#include <cuda_runtime.h>
#include <cuda_fp16.h>
#include <math.h>
#include <stdint.h>

typedef __half h16;

#define BATCH 4
#define SEQ   512
#define DIM   512
#define NH    8
#define NL    6
#define DFFN  2048
#define VOCAB 32000
#define ROWS  2048
#define NZ    32

// ---- split-weight stack: weights stored [N][2K] fp16 = [Bh|Bl] -------------
#define QKVL   ((size_t)1536*1024)
#define OFF_QKV 0
#define OFF_WO (NL*QKVL)                            // [512][1024]
#define OFF_W1 (OFF_WO + (size_t)NL*512*1024)       // [2048][1024]
#define OFF_W2 (OFF_W1 + (size_t)NL*2048*1024)      // [512][4096]
#define STACK  (OFF_W2 + (size_t)NL*512*4096)
#define OFF_PJ (2*STACK)
#define WTOT   (OFF_PJ + (size_t)VOCAB*1024)

__device__ __align__(256) h16   g_w  [WTOT];
__device__ __align__(256) float g_x  [ROWS*DIM];
__device__ __align__(256) float g_enc[ROWS*DIM];
__device__ __align__(256) h16   g_xsp[ROWS*2*DIM];        // [Ah|Ah]
__device__ __align__(256) h16   g_esp[ROWS*2*DIM];
__device__ __align__(256) h16   g_qsp[NZ*SEQ*128];        // per-head Q dup
__device__ __align__(256) h16   g_ksp[NZ*SEQ*128];        // per-head K [Kh|Kl]
__device__ __align__(256) float g_v  [ROWS*DIM];
__device__ __align__(256) h16   g_vt [BATCH*DIM*2*SEQ];   // V^T [Vh|Vl]
__device__ __align__(256) float g_sc [NZ*SEQ*SEQ];
__device__ __align__(256) h16   g_psp[NZ*SEQ*2*SEQ];      // probs dup
__device__ __align__(256) h16   g_asp[ROWS*2*DIM];        // attn out dup
__device__ __align__(256) h16   g_hsp[ROWS*2*DFFN];       // FFN hidden dup
__device__ __align__(256) float g_t  [2*ROWS*DIM];        // split-K partials

// ---------------- PTX helpers ------------------------------------------------
__device__ __forceinline__ uint32_t smem_u32(const void* p) {
    uint32_t a;
    asm("{ .reg .u64 t; cvta.to.shared.u64 t, %1; cvt.u32.u64 %0, t; }" : "=r"(a) : "l"(p));
    return a;
}
__device__ __forceinline__ void cpa16(uint32_t dst, const void* src) {
    asm volatile("cp.async.cg.shared.global [%0], [%1], 16;" :: "r"(dst), "l"(src));
}
#define CP_COMMIT() asm volatile("cp.async.commit_group;" ::: "memory")
#define CP_WAIT0()  asm volatile("cp.async.wait_group 0;" ::: "memory")
#define CP_WAIT1()  asm volatile("cp.async.wait_group 1;" ::: "memory")

__device__ __forceinline__ void ldsm4(uint32_t (&r)[4], uint32_t a) {
    asm volatile("ldmatrix.sync.aligned.m8n8.x4.shared.b16 {%0,%1,%2,%3}, [%4];"
        : "=r"(r[0]), "=r"(r[1]), "=r"(r[2]), "=r"(r[3]) : "r"(a));
}
__device__ __forceinline__ void mma16816(float (&d)[4], const uint32_t (&a)[4],
                                         const uint32_t b0, const uint32_t b1) {
    asm volatile("mma.sync.aligned.m16n8k16.row.col.f32.f16.f16.f32 "
        "{%0,%1,%2,%3}, {%4,%5,%6,%7}, {%8,%9}, {%0,%1,%2,%3};"
        : "+f"(d[0]), "+f"(d[1]), "+f"(d[2]), "+f"(d[3])
        : "r"(a[0]), "r"(a[1]), "r"(a[2]), "r"(a[3]), "r"(b0), "r"(b1));
}
__device__ __forceinline__ void split2(float v, h16& h, h16& l) {
    h = __float2half_rn(v);
    l = __float2half_rn(v - __half2float(h));
}

// ---------------- weight transpose + split: src[z,K,N] -> dst[z(dZ),N,2K] ----
__global__ void k_wsplit(const float* __restrict__ s, h16* __restrict__ d,
                         int K, int N, size_t dZ) {
    __shared__ float ts[32][33];
    int n0 = blockIdx.x*32, k0 = blockIdx.y*32;
    s += (size_t)blockIdx.z*K*N;
    d += (size_t)blockIdx.z*dZ;
    int tx = threadIdx.x, ty = threadIdx.y;
#pragma unroll
    for (int i=0;i<4;i++) ts[ty+8*i][tx] = s[(size_t)(k0+ty+8*i)*N + n0+tx];
    __syncthreads();
#pragma unroll
    for (int i=0;i<4;i++) {
        float v = ts[tx][ty+8*i];
        h16 h,l; split2(v,h,l);
        h16* dp = d + (size_t)(n0+ty+8*i)*2*K + k0 + tx;
        dp[0]=h; dp[K]=l;                     // [Bh|Bl]
    }
}

// ---------------- V transpose + split: V[2048][512] -> vt[b][c][2*512] -------
__global__ void k_vt(const float* __restrict__ V, h16* __restrict__ VT) {
    __shared__ float ts[32][33];
    int b = blockIdx.z;
    int s0 = blockIdx.x*32, c0 = blockIdx.y*32;
    int tx = threadIdx.x, ty = threadIdx.y;
#pragma unroll
    for (int i=0;i<4;i++) ts[ty+8*i][tx] = V[((size_t)b*SEQ + s0+ty+8*i)*DIM + c0+tx];
    __syncthreads();
#pragma unroll
    for (int i=0;i<4;i++) {
        float v = ts[tx][ty+8*i];
        h16 h,l; split2(v,h,l);
        h16* dp = VT + ((size_t)b*DIM + c0+ty+8*i)*(2*SEQ) + s0 + tx;
        dp[0]=h; dp[SEQ]=l;                   // [Vh|Vl]
    }
}

// ---------------- unified fp16 mma GEMM --------------------------------------
enum { EPI_PLAIN=0, EPI_QKV=1, EPI_SCORES=2, EPI_AV=3 };

template<int BM, int BN, int MODE>
__global__ void __launch_bounds__(256) k_gemm(
    int M, int N, int KK,
    const h16* __restrict__ A, const h16* __restrict__ B,
    int aRS, int bRS, size_t aZ, size_t bZ, size_t cZ,
    float* __restrict__ C, h16* __restrict__ S, h16* __restrict__ S2,
    int secOff, int sO0, int sO1, int sRS,
    const float* __restrict__ bias, int act,
    const int* __restrict__ tok, int causal)
{
    constexpr int ASZ = BM*128;
    constexpr int BSZ = BN*128;
    constexpr int STG = ASZ+BSZ;
    constexpr int AM  = BM/32;
    constexpr int NT  = BN/32;
    constexpr int WME = BM/2;
    constexpr int WNE = BN/4;
    extern __shared__ char sm[];
    uint32_t smBase = smem_u32(sm);

    int tid=threadIdx.x, lane=tid&31, wid=tid>>5;
    int wm=wid>>2, wn=wid&3;
    int m0=blockIdx.y*BM, n0=blockIdx.x*BN;
    int z=blockIdx.z;
    A += (size_t)z*aZ;
    if (MODE==EPI_AV) B += (((size_t)(z>>3)*DIM) + (size_t)(z&7)*64) * 1024;
    else              B += (size_t)z*bZ;

    float acc[AM][NT][4];
#pragma unroll
    for (int i=0;i<AM;i++)
#pragma unroll
        for (int j=0;j<NT;j++)
#pragma unroll
            for (int r=0;r<4;r++) acc[i][j][r]=0.f;

    auto loadStage = [&](int t, int s) {
        uint32_t st = smBase + s*STG;
        int k0 = t*64;
#pragma unroll
        for (int i=0;i<BM/32;i++) {
            int idx = tid + i*256;
            int r = idx>>3, c = idx&7;
            cpa16(st + r*128 + ((c^(r&7))<<4), A + (size_t)(m0+r)*aRS + k0 + c*8);
        }
#pragma unroll
        for (int i=0;i<BN/32;i++) {
            int idx = tid + i*256;
            int r = idx>>3, c = idx&7;
            cpa16(st + ASZ + r*128 + ((c^(r&7))<<4), B + (size_t)(n0+r)*bRS + k0 + c*8);
        }
    };

    int KT = KK/64;
    loadStage(0,0); CP_COMMIT();
    if (KT>1) { loadStage(1,1); CP_COMMIT(); }

    for (int t=0; t<KT; t++) {
        if (t+2<KT) CP_WAIT1(); else CP_WAIT0();
        __syncthreads();
        if (t+2<KT) { loadStage(t+2, (t+2)%3); CP_COMMIT(); }
        uint32_t aB = smBase + (t%3)*STG;
        uint32_t bB = aB + ASZ;
#pragma unroll
        for (int ks=0; ks<4; ks++) {
            uint32_t af[AM][4];
#pragma unroll
            for (int i=0;i<AM;i++) {
                int r = wm*WME + i*16 + (lane&15);
                int c = ks*2 + (lane>>4);
                ldsm4(af[i], aB + r*128 + ((c^(r&7))<<4));
            }
            uint32_t bfr[NT][2];
#pragma unroll
            for (int j=0;j<NT;j+=2) {
                uint32_t q[4];
                int r = wn*WNE + j*8 + (lane&7) + ((lane>>4)<<3);
                int c = ks*2 + ((lane>>3)&1);
                ldsm4(q, bB + r*128 + ((c^(r&7))<<4));
                bfr[j][0]=q[0]; bfr[j][1]=q[1]; bfr[j+1][0]=q[2]; bfr[j+1][1]=q[3];
            }
#pragma unroll
            for (int i=0;i<AM;i++)
#pragma unroll
                for (int j=0;j<NT;j++)
                    mma16816(acc[i][j], af[i], bfr[j][0], bfr[j][1]);
        }
    }

    // ---- epilogue ----
#pragma unroll
    for (int i=0;i<AM;i++) {
#pragma unroll
        for (int j=0;j<NT;j++) {
#pragma unroll
            for (int r=0;r<4;r++) {
                int row = m0 + wm*WME + i*16 + (lane>>2) + ((r>>1)<<3);
                int col = n0 + wn*WNE + j*8 + ((lane&3)<<1) + (r&1);
                float v = acc[i][j][r];
                if (MODE==EPI_PLAIN) {
                    if (bias && z==0) v += __ldg(&bias[col]);
                    if (act)  v = v>0.f ? v : 0.01f*v;
                    if (C) C[(size_t)z*cZ + (size_t)row*N + col] = v;
                    if (S) {
                        h16 h = __float2half_rn(v);
                        h16* sp = S + (size_t)row*sRS;
                        sp[col+sO0]=h; sp[col+sO1]=h;        // dup hi (A-style)
                    }
                } else if (MODE==EPI_QKV) {
                    int gc = col + secOff;
                    int b = row>>9, s = row&511;
                    if (gc < 512) {            // Q: dup hi per head
                        int h = gc>>6, d = gc&63;
                        h16* sp = S + ((size_t)((b<<3)+h)*512 + s)*128 + d;
                        h16 hh = __float2half_rn(v);
                        sp[0]=hh; sp[64]=hh;
                    } else if (gc < 1024) {    // K: [Kh|Kl] per head
                        int c = gc-512; int h = c>>6, d = c&63;
                        h16* sp = S2 + ((size_t)((b<<3)+h)*512 + s)*128 + d;
                        h16 hh,ll; split2(v,hh,ll);
                        sp[0]=hh; sp[64]=ll;
                    } else {                   // V: fp32 staging
                        C[(size_t)row*512 + gc-1024] = v;
                    }
                } else if (MODE==EPI_SCORES) {
                    bool mk = (tok[(z>>3)*512 + col]==0) || (causal && col>row);
                    C[(size_t)z*cZ + (size_t)row*512 + col] = mk ? 1e-9f : v*0.125f;
                } else {                       // EPI_AV: dup-hi attn out
                    int grow = ((z>>3)<<9) + row;
                    int gcol = ((z&7)<<6) + col;
                    h16 hh = __float2half_rn(v);
                    h16* sp = S + (size_t)grow*1024;
                    sp[gcol]=hh; sp[gcol+512]=hh;
                }
            }
        }
    }
}

// ---------------- embedding + PE ---------------------------------------------
__global__ void k_embed(const int* __restrict__ tok, const float* __restrict__ emb,
                        float* __restrict__ o, h16* __restrict__ os) {
    int idx = blockIdx.x*blockDim.x + threadIdx.x;
    int d = idx&(DIM-1), bs = idx>>9, s = bs&(SEQ-1);
    float pe = 0.f;
    if (s>0 && d>0) {
        double ang = (double)s / pow(10000.0, 2.0*(double)d/(double)DIM);
        pe = (float)((d&1) ? cos(ang) : sin(ang));
    }
    float v = emb[(size_t)tok[bs]*DIM + d] + pe;
    o[idx] = v;
    h16 h = __float2half_rn(v);
    h16* sp = os + (size_t)bs*(2*DIM) + d;
    sp[0]=h; sp[DIM]=h;
}

// ---------------- warp-per-row softmax -> dup-hi probs -----------------------
__global__ void k_softmax(const float* __restrict__ SC, h16* __restrict__ P) {
    int row = blockIdx.x*8 + (threadIdx.x>>5);
    int lane = threadIdx.x&31;
    const float* p = SC + (size_t)row*SEQ;
    float v[16];
#pragma unroll
    for (int i=0;i<4;i++) {
        float4 f = *(const float4*)(p + i*128 + lane*4);
        v[4*i]=f.x; v[4*i+1]=f.y; v[4*i+2]=f.z; v[4*i+3]=f.w;
    }
    float m = v[0];
#pragma unroll
    for (int i=1;i<16;i++) m = fmaxf(m, v[i]);
#pragma unroll
    for (int o=16;o;o>>=1) m = fmaxf(m, __shfl_xor_sync(0xffffffffu, m, o));
    float s = 0.f;
#pragma unroll
    for (int i=0;i<16;i++) { v[i] = expf(v[i]-m); s += v[i]; }
#pragma unroll
    for (int o=16;o;o>>=1) s += __shfl_xor_sync(0xffffffffu, s, o);
    float inv = 1.f/s;
    h16* sp = P + (size_t)row*1024;
#pragma unroll
    for (int i=0;i<4;i++) {
#pragma unroll
        for (int k=0;k<4;k++) {
            int idx = i*128 + lane*4 + k;
            h16 h = __float2half_rn(v[4*i+k]*inv);
            sp[idx]=h; sp[512+idx]=h;
        }
    }
}

// ---------------- residual + LN (sums split-K partials) ----------------------
__global__ void k_lnres(const float* __restrict__ t, const float* __restrict__ t2,
                        const float* __restrict__ r,
                        const float* __restrict__ g, const float* __restrict__ be,
                        float* __restrict__ o, h16* __restrict__ os) {
    int row = blockIdx.x, tid = threadIdx.x;
    __shared__ float red[256];
    size_t o0 = (size_t)row*DIM;
    float a  = t[o0+tid]     + t2[o0+tid]     + r[o0+tid];
    float b2 = t[o0+tid+256] + t2[o0+tid+256] + r[o0+tid+256];
    red[tid] = a+b2;
    __syncthreads();
    for (int s=128;s>0;s>>=1) { if (tid<s) red[tid]+=red[tid+s]; __syncthreads(); }
    float mean = red[0]*(1.f/DIM);
    __syncthreads();
    float da = a-mean, db = b2-mean;
    red[tid] = da*da + db*db;
    __syncthreads();
    for (int s=128;s>0;s>>=1) { if (tid<s) red[tid]+=red[tid+s]; __syncthreads(); }
    float inv = 1.f/sqrtf(red[0]*(1.f/DIM) + 1e-6f);
    float va = da*inv*g[tid] + be[tid];
    float vb = db*inv*g[tid+256] + be[tid+256];
    o[o0+tid] = va; o[o0+tid+256] = vb;
    h16* sp = os + (size_t)row*(2*DIM);
    h16 ha = __float2half_rn(va), hb = __float2half_rn(vb);
    sp[tid]=ha;     sp[DIM+tid]=ha;
    sp[tid+256]=hb; sp[DIM+tid+256]=hb;
}

// ---------------- host --------------------------------------------------------
#define SM_128_128 (3*(128+128)*128)   // 98304
#define SM_64_128  (3*(64+128)*128)    // 73728
#define SM_64_64   (3*(64+64)*128)     // 49152

extern "C" void kernel_launch(void* const* d_in, const int* in_sizes, int n_in,
                              void* d_out, int out_size) {
    const int*   etok = (const int*)d_in[0];
    const int*   dtok = (const int*)d_in[1];
    const float* eemb = (const float*)d_in[2];
    const float* demb = (const float*)d_in[3];
    const float* pw   = (const float*)d_in[4];
    const float* ep[12]; const float* dp[12];
    for (int i=0;i<12;i++) { ep[i]=(const float*)d_in[5+i]; dp[i]=(const float*)d_in[17+i]; }

    cudaFuncSetAttribute(k_gemm<128,128,EPI_PLAIN>,  cudaFuncAttributeMaxDynamicSharedMemorySize, SM_128_128);
    cudaFuncSetAttribute(k_gemm<128,128,EPI_QKV>,    cudaFuncAttributeMaxDynamicSharedMemorySize, SM_128_128);
    cudaFuncSetAttribute(k_gemm<128,128,EPI_SCORES>, cudaFuncAttributeMaxDynamicSharedMemorySize, SM_128_128);
    cudaFuncSetAttribute(k_gemm<64,128,EPI_PLAIN>,   cudaFuncAttributeMaxDynamicSharedMemorySize, SM_64_128);
    cudaFuncSetAttribute(k_gemm<64,128,EPI_QKV>,     cudaFuncAttributeMaxDynamicSharedMemorySize, SM_64_128);
    cudaFuncSetAttribute(k_gemm<64,64,EPI_AV>,       cudaFuncAttributeMaxDynamicSharedMemorySize, SM_64_64);

    h16 *w,*xsp,*esp,*qsp,*ksp,*vt,*psp,*asp,*hsp;
    float *x,*enc,*v,*sc,*t;
    cudaGetSymbolAddress((void**)&w,   g_w);
    cudaGetSymbolAddress((void**)&x,   g_x);   cudaGetSymbolAddress((void**)&enc, g_enc);
    cudaGetSymbolAddress((void**)&xsp, g_xsp); cudaGetSymbolAddress((void**)&esp, g_esp);
    cudaGetSymbolAddress((void**)&qsp, g_qsp); cudaGetSymbolAddress((void**)&ksp, g_ksp);
    cudaGetSymbolAddress((void**)&v,   g_v);   cudaGetSymbolAddress((void**)&vt,  g_vt);
    cudaGetSymbolAddress((void**)&sc,  g_sc);  cudaGetSymbolAddress((void**)&psp, g_psp);
    cudaGetSymbolAddress((void**)&asp, g_asp); cudaGetSymbolAddress((void**)&hsp, g_hsp);
    cudaGetSymbolAddress((void**)&t,   g_t);
    float* t2 = t + (size_t)ROWS*DIM;

    // ---- weight conversion: [K,N] fp32 -> [N,2K] fp16 [Bh|Bl] ----
    dim3 wb(32,8);
    for (int st=0; st<2; st++) {
        const float* const* P = st ? dp : ep;
        h16* wq = w + st*STACK;
        k_wsplit<<<dim3(16,16,NL), wb>>>(P[0], wq+OFF_QKV,            512, 512, QKVL);
        k_wsplit<<<dim3(16,16,NL), wb>>>(P[1], wq+OFF_QKV+ 512*1024,  512, 512, QKVL);
        k_wsplit<<<dim3(16,16,NL), wb>>>(P[2], wq+OFF_QKV+1024*1024,  512, 512, QKVL);
        k_wsplit<<<dim3(16,16,NL), wb>>>(P[3], wq+OFF_WO,             512, 512, (size_t)512*1024);
        k_wsplit<<<dim3(64,16,NL), wb>>>(P[6], wq+OFF_W1,             512, 2048,(size_t)2048*1024);
        k_wsplit<<<dim3(16,64,NL), wb>>>(P[8], wq+OFF_W2,            2048, 512, (size_t)512*4096);
    }
    k_wsplit<<<dim3(1000,16,1), wb>>>(pw, w+OFF_PJ, 512, VOCAB, 0);

    const size_t MN = (size_t)ROWS*DIM;

    for (int st=0; st<2; st++) {
        const int*   tokA = st ? dtok : etok;
        const float* const* P = st ? dp : ep;
        h16*   wq  = w + st*STACK;
        float* res = st ? x : enc;
        h16*   rsp = st ? xsp : esp;

        k_embed<<<(ROWS*DIM)/256,256>>>(tokA, st?demb:eemb, res, rsp);

        for (int l=0; l<NL; l++) {
            const h16* Wqkv = wq + OFF_QKV + l*QKVL;
            const h16* Wo   = wq + OFF_WO + (size_t)l*512*1024;
            const h16* W1   = wq + OFF_W1 + (size_t)l*2048*1024;
            const h16* W2   = wq + OFF_W2 + (size_t)l*512*4096;
            int nAtt = st ? 2 : 1;
            for (int a=0; a<nAtt; a++) {
                const int* tokKV = (st && a==1) ? etok : tokA;
                int causal = (st && a==0) ? 1 : 0;
                if (!st || a==0) {
                    k_gemm<128,128,EPI_QKV><<<dim3(12,16,1),256,SM_128_128>>>(
                        ROWS,1536,1024, rsp,Wqkv, 1024,1024, 0,0,0,
                        v, qsp,ksp, 0, 0,0,0, nullptr,0, nullptr,0);
                } else {
                    k_gemm<64,128,EPI_QKV><<<dim3(4,32,1),256,SM_64_128>>>(
                        ROWS,512,1024, rsp,Wqkv, 1024,1024, 0,0,0,
                        nullptr, qsp,nullptr, 0, 0,0,0, nullptr,0, nullptr,0);
                    k_gemm<128,128,EPI_QKV><<<dim3(8,16,1),256,SM_128_128>>>(
                        ROWS,1024,1024, esp,Wqkv+(size_t)512*1024, 1024,1024, 0,0,0,
                        v, nullptr,ksp, 512, 0,0,0, nullptr,0, nullptr,0);
                }
                k_vt<<<dim3(16,16,BATCH), wb>>>(v, vt);
                k_gemm<128,128,EPI_SCORES><<<dim3(4,4,NZ),256,SM_128_128>>>(
                    SEQ,SEQ,128, qsp,ksp, 128,128, (size_t)SEQ*128,(size_t)SEQ*128,(size_t)SEQ*SEQ,
                    sc, nullptr,nullptr, 0, 0,0,0, nullptr,0, tokKV,causal);
                k_softmax<<<NZ*SEQ/8,256>>>(sc, psp);
                k_gemm<64,64,EPI_AV><<<dim3(1,8,NZ),256,SM_64_64>>>(
                    SEQ,64,1024, psp,vt, 1024,1024, (size_t)SEQ*1024,0,0,
                    nullptr, asp,nullptr, 0, 0,0,0, nullptr,0, nullptr,0);
                k_gemm<64,128,EPI_PLAIN><<<dim3(4,32,2),256,SM_64_128>>>(
                    ROWS,512,512, asp,Wo, 1024,1024, 512,512,MN,
                    t, nullptr,nullptr, 0, 0,0,0, nullptr,0, nullptr,0);
                k_lnres<<<ROWS,256>>>(t, t2, res, P[4]+l*DIM, P[5]+l*DIM, res, rsp);
            }
            // FFN
            k_gemm<128,128,EPI_PLAIN><<<dim3(16,16,1),256,SM_128_128>>>(
                ROWS,DFFN,1024, rsp,W1, 1024,1024, 0,0,0,
                nullptr, hsp,nullptr, 0, 0,DFFN,2*DFFN, P[7]+l*DFFN,1, nullptr,0);
            k_gemm<64,128,EPI_PLAIN><<<dim3(4,32,2),256,SM_64_128>>>(
                ROWS,512,2048, hsp,W2, 4096,4096, 2048,2048,MN,
                t, nullptr,nullptr, 0, 0,0,0, P[9]+l*DIM,0, nullptr,0);
            k_lnres<<<ROWS,256>>>(t, t2, res, P[10]+l*DIM, P[11]+l*DIM, res, rsp);
        }
    }

    // ---- final vocab projection ----
    k_gemm<128,128,EPI_PLAIN><<<dim3(250,16,1),256,SM_128_128>>>(
        ROWS,VOCAB,1024, xsp, w+OFF_PJ, 1024,1024, 0,0,0,
        (float*)d_out, nullptr,nullptr, 0, 0,0,0, nullptr,0, nullptr,0);
}